// round 6
// baseline (speedup 1.0000x reference)
#include <cuda_runtime.h>
#include <cuda_fp16.h>
#include <cstdint>

// Problem constants
#define B_  2
#define L_  16384
#define C_  512
#define H_  16
#define D_  32
#define K_  7
#define SCALE_ 0.17677669529663687f   // 32^-0.5

// Scratch (device globals)
__device__ float  g_qkv[(size_t)B_ * L_ * 3 * C_];   // (B*L, 1536) fp32
__device__ __half g_aoh[(size_t)B_ * L_ * C_];       // attention out, fp16
__device__ __half g_xh [(size_t)B_ * L_ * C_];       // x, fp16
__device__ __half g_w1h[(size_t)3 * C_ * C_];        // qkv_w, fp16
__device__ __half g_w2h[(size_t)C_ * C_];            // proj_w, fp16

// Elementwise f32 -> f16 (rn); n4 = element count / 4
__global__ void cvt_half_kernel(const float* __restrict__ in,
                                __half* __restrict__ out, int n4)
{
    int i = blockIdx.x * blockDim.x + threadIdx.x;
    if (i < n4) {
        float4 v = ((const float4*)in)[i];
        __half2 h0 = __floats2half2_rn(v.x, v.y);
        __half2 h1 = __floats2half2_rn(v.z, v.w);
        uint2 p;
        p.x = *(unsigned*)&h0;
        p.y = *(unsigned*)&h1;
        ((uint2*)out)[i] = p;
    }
}

// ---------------------------------------------------------------------------
// FP16 tensor-core GEMM (f32 accum): C[M,N] = A[M,K] @ W[N,K]^T + bias[N]
// Block 128x256x32, 512 threads (16 warps), warp tile 32x64, mma.m16n8k16,
// ldmatrix.x4, 4-stage cp.async pipeline, ONE barrier per k-iter.
// Requires M%128==0, N%256==0, K%32==0.
// ---------------------------------------------------------------------------
#define GBM 128
#define GBN 256
#define GBK 32
#define ROWH 40                       // halves per smem row (32 data + 8 pad)
#define ROWB (ROWH * 2)               // 80 bytes
#define A_BYT (GBM * ROWB)            // 10240
#define B_BYT (GBN * ROWB)            // 20480
#define STG   (A_BYT + B_BYT)         // 30720
#define NSTG  4
#define SMEM_REQ (NSTG * STG)         // 122880

__device__ __forceinline__ void mma16(float* d, const unsigned* a, const unsigned* b) {
    asm volatile(
        "mma.sync.aligned.m16n8k16.row.col.f32.f16.f16.f32 "
        "{%0,%1,%2,%3},{%4,%5,%6,%7},{%8,%9},{%0,%1,%2,%3};\n"
        : "+f"(d[0]), "+f"(d[1]), "+f"(d[2]), "+f"(d[3])
        : "r"(a[0]), "r"(a[1]), "r"(a[2]), "r"(a[3]), "r"(b[0]), "r"(b[1]));
}

__device__ __forceinline__ void ldsm4(unsigned* r, uint32_t addr) {
    asm volatile(
        "ldmatrix.sync.aligned.m8n8.x4.shared.b16 {%0,%1,%2,%3}, [%4];"
        : "=r"(r[0]), "=r"(r[1]), "=r"(r[2]), "=r"(r[3]) : "r"(addr));
}

__global__ __launch_bounds__(512, 1) void gemm_f16(
    const __half* __restrict__ A, const __half* __restrict__ W,
    const float* __restrict__ bias, float* __restrict__ Co,
    int M, int N, int Kd)
{
    extern __shared__ char smem_raw[];
    uint32_t base;
    asm("{ .reg .u64 t; cvta.to.shared.u64 t, %1; cvt.u32.u64 %0, t; }"
        : "=r"(base) : "l"(smem_raw));

    const int tid  = threadIdx.x;
    const int lane = tid & 31;
    const int warp = tid >> 5;
    const int bm = blockIdx.y * GBM;
    const int bn = blockIdx.x * GBN;
    const int wm0 = (warp >> 2) * 32;   // 0,32,64,96
    const int wn0 = (warp & 3) * 64;    // 0,64,128,192
    const int NT = Kd / GBK;

    float acc[2][8][4];
#pragma unroll
    for (int i = 0; i < 2; i++)
#pragma unroll
        for (int j = 0; j < 8; j++)
#pragma unroll
            for (int c = 0; c < 4; c++) acc[i][j][c] = 0.f;

    // Stage loader: tile kt -> slot. 512 threads: A=512 chunks (1/t), B=1024 (2/t)
    auto load_stage = [&](int kt, int slot) {
        const int k0 = kt * GBK;
        const uint32_t sa = base + slot * STG;
        const uint32_t sb = sa + A_BYT;
        {
            int r = tid >> 2, c = tid & 3;
            uint32_t dst = sa + r * ROWB + c * 16;
            const __half* src = A + (size_t)(bm + r) * Kd + k0 + c * 8;
            asm volatile("cp.async.cg.shared.global [%0], [%1], 16;"
                         :: "r"(dst), "l"(src));
        }
#pragma unroll
        for (int i = 0; i < 2; i++) {
            int idx = tid + i * 512;
            int r = idx >> 2, c = idx & 3;
            uint32_t dst = sb + r * ROWB + c * 16;
            const __half* src = W + (size_t)(bn + r) * Kd + k0 + c * 8;
            asm volatile("cp.async.cg.shared.global [%0], [%1], 16;"
                         :: "r"(dst), "l"(src));
        }
        asm volatile("cp.async.commit_group;");
    };

    // ldmatrix lane addressing
    const int a_row = (lane & 15);
    const int a_k8  = (lane >> 4) * 8;
    const int b_row = (lane & 7) + ((lane >> 4) & 1) * 8;
    const int b_k8  = ((lane >> 3) & 1) * 8;

    // Prologue: 3 stages in flight
    load_stage(0, 0);
    load_stage(1, 1);
    load_stage(2, 2);

    for (int kt = 0; kt < NT; kt++) {
        const int slot = kt & (NSTG - 1);

        if (kt < NT - 2)       asm volatile("cp.async.wait_group 2;");
        else if (kt == NT - 2) asm volatile("cp.async.wait_group 1;");
        else                   asm volatile("cp.async.wait_group 0;");
        __syncthreads();

        // Prefetch tile kt+3 into slot (kt-1)%4: all warps are past iter kt-1.
        if (kt + 3 < NT) load_stage(kt + 3, (kt + 3) & (NSTG - 1));

        const uint32_t sa = base + slot * STG;
        const uint32_t sb = sa + A_BYT;

#pragma unroll
        for (int ks = 0; ks < 2; ks++) {
            const int kb = ks * 16;
            unsigned af[2][4];
#pragma unroll
            for (int mt = 0; mt < 2; mt++)
                ldsm4(af[mt], sa + (wm0 + mt * 16 + a_row) * ROWB + (kb + a_k8) * 2);
            unsigned bf[8][2];
#pragma unroll
            for (int p = 0; p < 4; p++) {
                unsigned t[4];
                ldsm4(t, sb + (wn0 + p * 16 + b_row) * ROWB + (kb + b_k8) * 2);
                bf[p * 2 + 0][0] = t[0]; bf[p * 2 + 0][1] = t[1];
                bf[p * 2 + 1][0] = t[2]; bf[p * 2 + 1][1] = t[3];
            }
#pragma unroll
            for (int mt = 0; mt < 2; mt++)
#pragma unroll
                for (int nt = 0; nt < 8; nt++)
                    mma16(acc[mt][nt], af[mt], bf[nt]);
        }
    }

    // Epilogue: bias + store
    const int g  = lane >> 2;
    const int tq = lane & 3;
#pragma unroll
    for (int nt = 0; nt < 8; nt++) {
        int col = bn + wn0 + nt * 8 + tq * 2;
        float2 bb = *(const float2*)&bias[col];
#pragma unroll
        for (int mt = 0; mt < 2; mt++) {
            int row = bm + wm0 + mt * 16 + g;
            float2 o0, o1;
            o0.x = acc[mt][nt][0] + bb.x; o0.y = acc[mt][nt][1] + bb.y;
            o1.x = acc[mt][nt][2] + bb.x; o1.y = acc[mt][nt][3] + bb.y;
            *(float2*)(Co + (size_t)row * N + col) = o0;
            *(float2*)(Co + (size_t)(row + 8) * N + col) = o1;
        }
    }
}

// ---------------------------------------------------------------------------
// Neighborhood attention, K=7, D=32. fp32 in, fp16 out (feeds GEMM2).
// ---------------------------------------------------------------------------
#define TL 128

__global__ __launch_bounds__(128) void natt_kernel(
    const float* __restrict__ qkv, const float* __restrict__ rpb,
    __half* __restrict__ ao)
{
    __shared__ float ks[134][33];
    __shared__ float vs[134][33];

    const int b  = blockIdx.z;
    const int h  = blockIdx.y;
    const int l0 = blockIdx.x * TL;
    const int tid = threadIdx.x;

    const int ni0 = min(max(l0 - (K_ / 2), 0), L_ - K_);
    const int niL = min(max(l0 + TL - 1 - (K_ / 2), 0), L_ - K_);
    const int range = niL + K_ - ni0;   // <= 134

    for (int i = tid; i < range * D_; i += TL) {
        int r = i >> 5, d = i & 31;
        size_t base = ((size_t)(b * L_ + ni0 + r)) * (3 * C_) + h * D_ + d;
        ks[r][d] = qkv[base + C_];
        vs[r][d] = qkv[base + 2 * C_];
    }
    __syncthreads();

    const int l = l0 + tid;
    const float* qp = qkv + (size_t)(b * L_ + l) * (3 * C_) + h * D_;

    float q[D_];
#pragma unroll
    for (int d4 = 0; d4 < D_ / 4; d4++) {
        float4 v = *(const float4*)(qp + d4 * 4);
        q[d4 * 4 + 0] = v.x * SCALE_;
        q[d4 * 4 + 1] = v.y * SCALE_;
        q[d4 * 4 + 2] = v.z * SCALE_;
        q[d4 * 4 + 3] = v.w * SCALE_;
    }

    const int ni = min(max(l - (K_ / 2), 0), L_ - K_);
    float a[K_];
#pragma unroll
    for (int j = 0; j < K_; j++) {
        int r = ni + j - ni0;
        float dot = 0.f;
#pragma unroll
        for (int d = 0; d < D_; d++) dot += q[d] * ks[r][d];
        a[j] = dot + rpb[h * (2 * K_ - 1) + (ni + j - l + (K_ - 1))];
    }

    float m = a[0];
#pragma unroll
    for (int j = 1; j < K_; j++) m = fmaxf(m, a[j]);
    float s = 0.f;
#pragma unroll
    for (int j = 0; j < K_; j++) { a[j] = __expf(a[j] - m); s += a[j]; }
    float inv = 1.f / s;

    float o[D_];
#pragma unroll
    for (int d = 0; d < D_; d++) o[d] = 0.f;
#pragma unroll
    for (int j = 0; j < K_; j++) {
        float p = a[j] * inv;
        int r = ni + j - ni0;
#pragma unroll
        for (int d = 0; d < D_; d++) o[d] += p * vs[r][d];
    }

    __half* op = ao + (size_t)(b * L_ + l) * C_ + h * D_;
#pragma unroll
    for (int d2 = 0; d2 < D_ / 2; d2++) {
        __half2 hv = __floats2half2_rn(o[d2 * 2], o[d2 * 2 + 1]);
        *(__half2*)(op + d2 * 2) = hv;
    }
}

// ---------------------------------------------------------------------------
extern "C" void kernel_launch(void* const* d_in, const int* in_sizes, int n_in,
                              void* d_out, int out_size)
{
    const float* x      = (const float*)d_in[0];
    const float* qkv_w  = (const float*)d_in[1];
    const float* qkv_b  = (const float*)d_in[2];
    const float* rpb    = (const float*)d_in[3];
    const float* proj_w = (const float*)d_in[4];
    const float* proj_b = (const float*)d_in[5];
    float* out = (float*)d_out;

    float  *qkv;
    __half *aoh, *xh, *w1h, *w2h;
    cudaGetSymbolAddress((void**)&qkv, g_qkv);
    cudaGetSymbolAddress((void**)&aoh, g_aoh);
    cudaGetSymbolAddress((void**)&xh,  g_xh);
    cudaGetSymbolAddress((void**)&w1h, g_w1h);
    cudaGetSymbolAddress((void**)&w2h, g_w2h);

    cudaFuncSetAttribute(gemm_f16,
                         cudaFuncAttributeMaxDynamicSharedMemorySize, SMEM_REQ);

    const int M = B_ * L_;            // 32768

    // 0) Convert GEMM operands to fp16
    {
        int n4 = (M * C_) / 4;
        cvt_half_kernel<<<(n4 + 255) / 256, 256>>>(x, xh, n4);
        int w1 = (3 * C_ * C_) / 4;
        cvt_half_kernel<<<(w1 + 255) / 256, 256>>>(qkv_w, w1h, w1);
        int w2 = (C_ * C_) / 4;
        cvt_half_kernel<<<(w2 + 255) / 256, 256>>>(proj_w, w2h, w2);
    }

    // 1) QKV = x @ qkv_w^T + qkv_b    (M x 1536)
    {
        dim3 grid((3 * C_) / GBN, M / GBM);
        gemm_f16<<<grid, 512, SMEM_REQ>>>(xh, w1h, qkv_b, qkv, M, 3 * C_, C_);
    }

    // 2) Neighborhood attention -> aoh (M x 512, fp16)
    {
        dim3 grid(L_ / TL, H_, B_);
        natt_kernel<<<grid, TL>>>(qkv, rpb, aoh);
    }

    // 3) out = aoh @ proj_w^T + proj_b (M x 512)
    {
        dim3 grid(C_ / GBN, M / GBM);
        gemm_f16<<<grid, 512, SMEM_REQ>>>(aoh, w2h, proj_b, out, M, C_, C_);
    }
}

// round 7
// speedup vs baseline: 1.0001x; 1.0001x over previous
#include <cuda_runtime.h>
#include <cuda_fp16.h>
#include <cstdint>

// Problem constants
#define B_  2
#define L_  16384
#define C_  512
#define H_  16
#define D_  32
#define K_  7
#define SCALE_ 0.17677669529663687f   // 32^-0.5

// Scratch (device globals)
__device__ float  g_qkv[(size_t)B_ * L_ * 3 * C_];   // (B*L, 1536) fp32
__device__ __half g_aoh[(size_t)B_ * L_ * C_];       // attention out, fp16
__device__ __half g_xh [(size_t)B_ * L_ * C_];       // x, fp16
__device__ __half g_w1h[(size_t)3 * C_ * C_];        // qkv_w, fp16
__device__ __half g_w2h[(size_t)C_ * C_];            // proj_w, fp16

// Elementwise f32 -> f16 (rn); n4 = element count / 4
__global__ void cvt_half_kernel(const float* __restrict__ in,
                                __half* __restrict__ out, int n4)
{
    int i = blockIdx.x * blockDim.x + threadIdx.x;
    if (i < n4) {
        float4 v = ((const float4*)in)[i];
        __half2 h0 = __floats2half2_rn(v.x, v.y);
        __half2 h1 = __floats2half2_rn(v.z, v.w);
        uint2 p;
        p.x = *(unsigned*)&h0;
        p.y = *(unsigned*)&h1;
        ((uint2*)out)[i] = p;
    }
}

// ---------------------------------------------------------------------------
// FP16 tensor-core GEMM (f32 accum): C[M,N] = A[M,K] @ W[N,K]^T + bias[N]
// Block 128x256x32, 512 threads (16 warps), warp tile 32x64, mma.m16n8k16,
// ldmatrix.x4, 4-stage cp.async pipeline, ONE barrier per k-iter.
// Requires M%128==0, N%256==0, K%32==0.
// ---------------------------------------------------------------------------
#define GBM 128
#define GBN 256
#define GBK 32
#define ROWH 40                       // halves per smem row (32 data + 8 pad)
#define ROWB (ROWH * 2)               // 80 bytes
#define A_BYT (GBM * ROWB)            // 10240
#define B_BYT (GBN * ROWB)            // 20480
#define STG   (A_BYT + B_BYT)         // 30720
#define NSTG  4
#define SMEM_REQ (NSTG * STG)         // 122880

__device__ __forceinline__ void mma16(float* d, const unsigned* a, const unsigned* b) {
    asm volatile(
        "mma.sync.aligned.m16n8k16.row.col.f32.f16.f16.f32 "
        "{%0,%1,%2,%3},{%4,%5,%6,%7},{%8,%9},{%0,%1,%2,%3};\n"
        : "+f"(d[0]), "+f"(d[1]), "+f"(d[2]), "+f"(d[3])
        : "r"(a[0]), "r"(a[1]), "r"(a[2]), "r"(a[3]), "r"(b[0]), "r"(b[1]));
}

__device__ __forceinline__ void ldsm4(unsigned* r, uint32_t addr) {
    asm volatile(
        "ldmatrix.sync.aligned.m8n8.x4.shared.b16 {%0,%1,%2,%3}, [%4];"
        : "=r"(r[0]), "=r"(r[1]), "=r"(r[2]), "=r"(r[3]) : "r"(addr));
}

__global__ __launch_bounds__(512, 1) void gemm_f16(
    const __half* __restrict__ A, const __half* __restrict__ W,
    const float* __restrict__ bias, float* __restrict__ Co,
    int M, int N, int Kd)
{
    extern __shared__ char smem_raw[];
    uint32_t base;
    asm("{ .reg .u64 t; cvta.to.shared.u64 t, %1; cvt.u32.u64 %0, t; }"
        : "=r"(base) : "l"(smem_raw));

    const int tid  = threadIdx.x;
    const int lane = tid & 31;
    const int warp = tid >> 5;
    const int bm = blockIdx.y * GBM;
    const int bn = blockIdx.x * GBN;
    const int wm0 = (warp >> 2) * 32;   // 0,32,64,96
    const int wn0 = (warp & 3) * 64;    // 0,64,128,192
    const int NT = Kd / GBK;

    float acc[2][8][4];
#pragma unroll
    for (int i = 0; i < 2; i++)
#pragma unroll
        for (int j = 0; j < 8; j++)
#pragma unroll
            for (int c = 0; c < 4; c++) acc[i][j][c] = 0.f;

    // Stage loader: tile kt -> slot. 512 threads: A=512 chunks (1/t), B=1024 (2/t)
    auto load_stage = [&](int kt, int slot) {
        const int k0 = kt * GBK;
        const uint32_t sa = base + slot * STG;
        const uint32_t sb = sa + A_BYT;
        {
            int r = tid >> 2, c = tid & 3;
            uint32_t dst = sa + r * ROWB + c * 16;
            const __half* src = A + (size_t)(bm + r) * Kd + k0 + c * 8;
            asm volatile("cp.async.cg.shared.global [%0], [%1], 16;"
                         :: "r"(dst), "l"(src));
        }
#pragma unroll
        for (int i = 0; i < 2; i++) {
            int idx = tid + i * 512;
            int r = idx >> 2, c = idx & 3;
            uint32_t dst = sb + r * ROWB + c * 16;
            const __half* src = W + (size_t)(bn + r) * Kd + k0 + c * 8;
            asm volatile("cp.async.cg.shared.global [%0], [%1], 16;"
                         :: "r"(dst), "l"(src));
        }
        asm volatile("cp.async.commit_group;");
    };

    // ldmatrix lane addressing
    const int a_row = (lane & 15);
    const int a_k8  = (lane >> 4) * 8;
    const int b_row = (lane & 7) + ((lane >> 4) & 1) * 8;
    const int b_k8  = ((lane >> 3) & 1) * 8;

    // Prologue: 3 stages in flight
    load_stage(0, 0);
    load_stage(1, 1);
    load_stage(2, 2);

    for (int kt = 0; kt < NT; kt++) {
        const int slot = kt & (NSTG - 1);

        if (kt < NT - 2)       asm volatile("cp.async.wait_group 2;");
        else if (kt == NT - 2) asm volatile("cp.async.wait_group 1;");
        else                   asm volatile("cp.async.wait_group 0;");
        __syncthreads();

        // Prefetch tile kt+3 into slot (kt-1)%4: all warps are past iter kt-1.
        if (kt + 3 < NT) load_stage(kt + 3, (kt + 3) & (NSTG - 1));

        const uint32_t sa = base + slot * STG;
        const uint32_t sb = sa + A_BYT;

#pragma unroll
        for (int ks = 0; ks < 2; ks++) {
            const int kb = ks * 16;
            unsigned af[2][4];
#pragma unroll
            for (int mt = 0; mt < 2; mt++)
                ldsm4(af[mt], sa + (wm0 + mt * 16 + a_row) * ROWB + (kb + a_k8) * 2);
            unsigned bf[8][2];
#pragma unroll
            for (int p = 0; p < 4; p++) {
                unsigned t[4];
                ldsm4(t, sb + (wn0 + p * 16 + b_row) * ROWB + (kb + b_k8) * 2);
                bf[p * 2 + 0][0] = t[0]; bf[p * 2 + 0][1] = t[1];
                bf[p * 2 + 1][0] = t[2]; bf[p * 2 + 1][1] = t[3];
            }
#pragma unroll
            for (int mt = 0; mt < 2; mt++)
#pragma unroll
                for (int nt = 0; nt < 8; nt++)
                    mma16(acc[mt][nt], af[mt], bf[nt]);
        }
    }

    // Epilogue: bias + store
    const int g  = lane >> 2;
    const int tq = lane & 3;
#pragma unroll
    for (int nt = 0; nt < 8; nt++) {
        int col = bn + wn0 + nt * 8 + tq * 2;
        float2 bb = *(const float2*)&bias[col];
#pragma unroll
        for (int mt = 0; mt < 2; mt++) {
            int row = bm + wm0 + mt * 16 + g;
            float2 o0, o1;
            o0.x = acc[mt][nt][0] + bb.x; o0.y = acc[mt][nt][1] + bb.y;
            o1.x = acc[mt][nt][2] + bb.x; o1.y = acc[mt][nt][3] + bb.y;
            *(float2*)(Co + (size_t)row * N + col) = o0;
            *(float2*)(Co + (size_t)(row + 8) * N + col) = o1;
        }
    }
}

// ---------------------------------------------------------------------------
// Neighborhood attention, K=7, D=32. fp32 in, fp16 out (feeds GEMM2).
// ---------------------------------------------------------------------------
#define TL 128

__global__ __launch_bounds__(128) void natt_kernel(
    const float* __restrict__ qkv, const float* __restrict__ rpb,
    __half* __restrict__ ao)
{
    __shared__ float ks[134][33];
    __shared__ float vs[134][33];

    const int b  = blockIdx.z;
    const int h  = blockIdx.y;
    const int l0 = blockIdx.x * TL;
    const int tid = threadIdx.x;

    const int ni0 = min(max(l0 - (K_ / 2), 0), L_ - K_);
    const int niL = min(max(l0 + TL - 1 - (K_ / 2), 0), L_ - K_);
    const int range = niL + K_ - ni0;   // <= 134

    for (int i = tid; i < range * D_; i += TL) {
        int r = i >> 5, d = i & 31;
        size_t base = ((size_t)(b * L_ + ni0 + r)) * (3 * C_) + h * D_ + d;
        ks[r][d] = qkv[base + C_];
        vs[r][d] = qkv[base + 2 * C_];
    }
    __syncthreads();

    const int l = l0 + tid;
    const float* qp = qkv + (size_t)(b * L_ + l) * (3 * C_) + h * D_;

    float q[D_];
#pragma unroll
    for (int d4 = 0; d4 < D_ / 4; d4++) {
        float4 v = *(const float4*)(qp + d4 * 4);
        q[d4 * 4 + 0] = v.x * SCALE_;
        q[d4 * 4 + 1] = v.y * SCALE_;
        q[d4 * 4 + 2] = v.z * SCALE_;
        q[d4 * 4 + 3] = v.w * SCALE_;
    }

    const int ni = min(max(l - (K_ / 2), 0), L_ - K_);
    float a[K_];
#pragma unroll
    for (int j = 0; j < K_; j++) {
        int r = ni + j - ni0;
        float dot = 0.f;
#pragma unroll
        for (int d = 0; d < D_; d++) dot += q[d] * ks[r][d];
        a[j] = dot + rpb[h * (2 * K_ - 1) + (ni + j - l + (K_ - 1))];
    }

    float m = a[0];
#pragma unroll
    for (int j = 1; j < K_; j++) m = fmaxf(m, a[j]);
    float s = 0.f;
#pragma unroll
    for (int j = 0; j < K_; j++) { a[j] = __expf(a[j] - m); s += a[j]; }
    float inv = 1.f / s;

    float o[D_];
#pragma unroll
    for (int d = 0; d < D_; d++) o[d] = 0.f;
#pragma unroll
    for (int j = 0; j < K_; j++) {
        float p = a[j] * inv;
        int r = ni + j - ni0;
#pragma unroll
        for (int d = 0; d < D_; d++) o[d] += p * vs[r][d];
    }

    __half* op = ao + (size_t)(b * L_ + l) * C_ + h * D_;
#pragma unroll
    for (int d2 = 0; d2 < D_ / 2; d2++) {
        __half2 hv = __floats2half2_rn(o[d2 * 2], o[d2 * 2 + 1]);
        *(__half2*)(op + d2 * 2) = hv;
    }
}

// ---------------------------------------------------------------------------
extern "C" void kernel_launch(void* const* d_in, const int* in_sizes, int n_in,
                              void* d_out, int out_size)
{
    const float* x      = (const float*)d_in[0];
    const float* qkv_w  = (const float*)d_in[1];
    const float* qkv_b  = (const float*)d_in[2];
    const float* rpb    = (const float*)d_in[3];
    const float* proj_w = (const float*)d_in[4];
    const float* proj_b = (const float*)d_in[5];
    float* out = (float*)d_out;

    float  *qkv;
    __half *aoh, *xh, *w1h, *w2h;
    cudaGetSymbolAddress((void**)&qkv, g_qkv);
    cudaGetSymbolAddress((void**)&aoh, g_aoh);
    cudaGetSymbolAddress((void**)&xh,  g_xh);
    cudaGetSymbolAddress((void**)&w1h, g_w1h);
    cudaGetSymbolAddress((void**)&w2h, g_w2h);

    cudaFuncSetAttribute(gemm_f16,
                         cudaFuncAttributeMaxDynamicSharedMemorySize, SMEM_REQ);

    const int M = B_ * L_;            // 32768

    // 0) Convert GEMM operands to fp16
    {
        int n4 = (M * C_) / 4;
        cvt_half_kernel<<<(n4 + 255) / 256, 256>>>(x, xh, n4);
        int w1 = (3 * C_ * C_) / 4;
        cvt_half_kernel<<<(w1 + 255) / 256, 256>>>(qkv_w, w1h, w1);
        int w2 = (C_ * C_) / 4;
        cvt_half_kernel<<<(w2 + 255) / 256, 256>>>(proj_w, w2h, w2);
    }

    // 1) QKV = x @ qkv_w^T + qkv_b    (M x 1536)
    {
        dim3 grid((3 * C_) / GBN, M / GBM);
        gemm_f16<<<grid, 512, SMEM_REQ>>>(xh, w1h, qkv_b, qkv, M, 3 * C_, C_);
    }

    // 2) Neighborhood attention -> aoh (M x 512, fp16)
    {
        dim3 grid(L_ / TL, H_, B_);
        natt_kernel<<<grid, TL>>>(qkv, rpb, aoh);
    }

    // 3) out = aoh @ proj_w^T + proj_b (M x 512)
    {
        dim3 grid(C_ / GBN, M / GBM);
        gemm_f16<<<grid, 512, SMEM_REQ>>>(aoh, w2h, proj_b, out, M, C_, C_);
    }
}